// round 1
// baseline (speedup 1.0000x reference)
#include <cuda_runtime.h>
#include <math.h>

// Shapes (fixed per problem)
#define S   128
#define R   256
#define CM  256
#define CZ  128
#define H   8
#define CH  32
#define HC  (H*CH)     // 256
#define MROWS (S*R)    // 32768

// ---------------- device scratch (no allocations allowed) ----------------
__device__ float g_m   [MROWS*CM];   // ln(msa)
__device__ float g_q   [MROWS*HC];
__device__ float g_k   [MROWS*HC];
__device__ float g_v   [MROWS*HC];
__device__ float g_g   [MROWS*HC];   // sigmoid gates
__device__ float g_bias[H*R*R];      // pair bias [h][i][j]
__device__ float g_w   [S*H*R*R];    // softmax weights
__device__ float g_o   [MROWS*HC];   // gated attention output

// ---------------- LayerNorm over C_M=256 (one block per row) ----------------
__global__ void ln_msa_kernel(const float* __restrict__ x,
                              const float* __restrict__ gamma,
                              const float* __restrict__ beta) {
    int row = blockIdx.x;
    int t = threadIdx.x;
    float v = x[(size_t)row*CM + t];
    float s1 = v, s2 = v*v;
    #pragma unroll
    for (int o = 16; o; o >>= 1) {
        s1 += __shfl_xor_sync(0xffffffffu, s1, o);
        s2 += __shfl_xor_sync(0xffffffffu, s2, o);
    }
    __shared__ float r1[8], r2[8];
    int w = t >> 5, lane = t & 31;
    if (lane == 0) { r1[w] = s1; r2[w] = s2; }
    __syncthreads();
    float ts1 = 0.f, ts2 = 0.f;
    #pragma unroll
    for (int i = 0; i < 8; ++i) { ts1 += r1[i]; ts2 += r2[i]; }
    float mu  = ts1 * (1.f/CM);
    float var = ts2 * (1.f/CM) - mu*mu;
    float rs  = rsqrtf(var + 1e-5f);
    g_m[(size_t)row*CM + t] = (v - mu)*rs*gamma[t] + beta[t];
}

// ------------- pair LayerNorm (C_Z=128) + project to bias [H,R,R] -------------
__global__ void pair_bias_kernel(const float* __restrict__ z,
                                 const float* __restrict__ gamma,
                                 const float* __restrict__ beta,
                                 const float* __restrict__ wb,
                                 const float* __restrict__ bb) {
    int ij = blockIdx.x;              // i*R + j
    int t  = threadIdx.x;             // 0..127
    float v = z[(size_t)ij*CZ + t];
    float s1 = v, s2 = v*v;
    #pragma unroll
    for (int o = 16; o; o >>= 1) {
        s1 += __shfl_xor_sync(0xffffffffu, s1, o);
        s2 += __shfl_xor_sync(0xffffffffu, s2, o);
    }
    __shared__ float r1[4], r2[4];
    int w = t >> 5, lane = t & 31;
    if (lane == 0) { r1[w] = s1; r2[w] = s2; }
    __syncthreads();
    float ts1 = r1[0]+r1[1]+r1[2]+r1[3];
    float ts2 = r2[0]+r2[1]+r2[2]+r2[3];
    float mu  = ts1 * (1.f/CZ);
    float var = ts2 * (1.f/CZ) - mu*mu;
    float rs  = rsqrtf(var + 1e-5f);
    float zn  = (v - mu)*rs*gamma[t] + beta[t];

    __shared__ float part[4][8];
    #pragma unroll
    for (int h = 0; h < H; ++h) {
        float p = zn * wb[t*H + h];
        #pragma unroll
        for (int o = 16; o; o >>= 1) p += __shfl_xor_sync(0xffffffffu, p, o);
        if (lane == 0) part[w][h] = p;
    }
    __syncthreads();
    if (t < H) {
        float sum = part[0][t] + part[1][t] + part[2][t] + part[3][t] + bb[t];
        g_bias[(size_t)t*(R*R) + ij] = sum;
    }
}

// ---------------- tiled fp32 GEMM: C[M,N] = A[M,K] @ B[K,N] ----------------
// EPI: 0 = none, 1 = +bias, 2 = sigmoid(x + bias)
template<int EPI>
__global__ void gemm_kernel(const float* __restrict__ A,
                            const float* __restrict__ B,
                            const float* __restrict__ bias,
                            float* __restrict__ C,
                            int M, int N, int K) {
    const int BM = 128, BN = 64, BK = 16;
    __shared__ float As[BK*BM];  // transposed: As[k][m]
    __shared__ float Bs[BK*BN];  // Bs[k][n]
    int tid = threadIdx.x;
    int tx = tid & 15, ty = tid >> 4;         // 16x16 thread grid
    int m0 = blockIdx.y * BM, n0 = blockIdx.x * BN;

    float acc[8][4];
    #pragma unroll
    for (int i = 0; i < 8; ++i)
        #pragma unroll
        for (int j = 0; j < 4; ++j) acc[i][j] = 0.f;

    for (int kt = 0; kt < K; kt += BK) {
        // A tile: 128x16 -> 512 float4, 2 per thread, store transposed
        #pragma unroll
        for (int l = 0; l < 2; ++l) {
            int f = tid + l*256;
            int row = f >> 2, c4 = (f & 3) * 4;
            float4 a = *(const float4*)(A + (size_t)(m0+row)*K + kt + c4);
            As[(c4+0)*BM + row] = a.x;
            As[(c4+1)*BM + row] = a.y;
            As[(c4+2)*BM + row] = a.z;
            As[(c4+3)*BM + row] = a.w;
        }
        // B tile: 16x64 -> 256 float4, 1 per thread
        {
            int row = tid >> 4, c4 = (tid & 15) * 4;
            *(float4*)(Bs + row*BN + c4) =
                *(const float4*)(B + (size_t)(kt+row)*N + n0 + c4);
        }
        __syncthreads();
        #pragma unroll
        for (int k = 0; k < BK; ++k) {
            float4 a0 = *(float4*)(As + k*BM + ty*8);
            float4 a1 = *(float4*)(As + k*BM + ty*8 + 4);
            float4 b0 = *(float4*)(Bs + k*BN + tx*4);
            float ar[8] = {a0.x,a0.y,a0.z,a0.w,a1.x,a1.y,a1.z,a1.w};
            float br[4] = {b0.x,b0.y,b0.z,b0.w};
            #pragma unroll
            for (int i = 0; i < 8; ++i)
                #pragma unroll
                for (int j = 0; j < 4; ++j)
                    acc[i][j] += ar[i]*br[j];
        }
        __syncthreads();
    }

    float bvals[4] = {0.f,0.f,0.f,0.f};
    if (EPI >= 1) {
        #pragma unroll
        for (int j = 0; j < 4; ++j) bvals[j] = bias[n0 + tx*4 + j];
    }
    #pragma unroll
    for (int i = 0; i < 8; ++i) {
        float4 out;
        float* o = &out.x;
        #pragma unroll
        for (int j = 0; j < 4; ++j) {
            float c = acc[i][j];
            if (EPI >= 1) c += bvals[j];
            if (EPI == 2) c = 1.f/(1.f + __expf(-c));
            o[j] = c;
        }
        *(float4*)(C + (size_t)(m0 + ty*8 + i)*N + n0 + tx*4) = out;
    }
}

// ------------- attention pass 1: softmax(QK^T/sqrt(C) + bias) -> g_w -------------
__global__ void attn_qk_kernel() {
    int sh = blockIdx.x;
    int s = sh >> 3, h = sh & 7;
    __shared__ float Ks[R*CH];     // XOR-swizzled [256][32]
    __shared__ float qb[8*32];
    int tid = threadIdx.x, warp = tid >> 5, lane = tid & 31;

    const float* Kp = g_k + (size_t)s*R*HC + h*CH;
    for (int idx = tid; idx < R*CH; idx += 256) {
        int r = idx >> 5, d = idx & 31;
        Ks[r*32 + (d ^ (r & 31))] = Kp[(size_t)r*HC + d];
    }
    __syncthreads();

    const float* Qp = g_q + (size_t)s*R*HC + h*CH;
    const float* Bb = g_bias + (size_t)h*R*R;
    float* Wp = g_w + (size_t)sh*R*R;

    for (int qi = 0; qi < 32; ++qi) {
        int qr = warp*32 + qi;
        qb[warp*32 + lane] = Qp[(size_t)qr*HC + lane];
        __syncwarp();
        float qreg[32];
        #pragma unroll
        for (int d = 0; d < 32; ++d) qreg[d] = qb[warp*32 + d];

        float l[8];
        float mx = -1e30f;
        const float* br = Bb + (size_t)qr*R;
        #pragma unroll
        for (int ch = 0; ch < 8; ++ch) {
            int j = ch*32 + lane;
            float acc = 0.f;
            #pragma unroll
            for (int d = 0; d < 32; ++d)
                acc += qreg[d] * Ks[j*32 + (d ^ lane)];
            float lg = acc*0.17677669529663687f + br[j];  // 1/sqrt(32)
            l[ch] = lg;
            mx = fmaxf(mx, lg);
        }
        #pragma unroll
        for (int o = 16; o; o >>= 1) mx = fmaxf(mx, __shfl_xor_sync(0xffffffffu, mx, o));
        float sum = 0.f;
        #pragma unroll
        for (int ch = 0; ch < 8; ++ch) { l[ch] = __expf(l[ch] - mx); sum += l[ch]; }
        #pragma unroll
        for (int o = 16; o; o >>= 1) sum += __shfl_xor_sync(0xffffffffu, sum, o);
        float inv = 1.f/sum;
        #pragma unroll
        for (int ch = 0; ch < 8; ++ch)
            Wp[(size_t)qr*R + ch*32 + lane] = l[ch]*inv;
        __syncwarp();   // protect qb before next iteration's write
    }
}

// ------------- attention pass 2: O = (W @ V) * gate -> g_o -------------
__global__ void attn_av_kernel() {
    int sh = blockIdx.x;
    int s = sh >> 3, h = sh & 7;
    __shared__ float Vs[R*CH];      // XOR-swizzled
    __shared__ float wbuf[8*256];
    int tid = threadIdx.x, warp = tid >> 5, lane = tid & 31;

    const float* Vp = g_v + (size_t)s*R*HC + h*CH;
    for (int idx = tid; idx < R*CH; idx += 256) {
        int r = idx >> 5, d = idx & 31;
        Vs[r*32 + (d ^ (r & 31))] = Vp[(size_t)r*HC + d];
    }
    __syncthreads();

    const float* Wp = g_w + (size_t)sh*R*R;
    const float* Gp = g_g + (size_t)s*R*HC + h*CH;
    float* Op = g_o + (size_t)s*R*HC + h*CH;

    for (int qi = 0; qi < 32; ++qi) {
        int qr = warp*32 + qi;
        #pragma unroll
        for (int ch = 0; ch < 8; ++ch)
            wbuf[warp*256 + ch*32 + lane] = Wp[(size_t)qr*R + ch*32 + lane];
        __syncwarp();
        float acc = 0.f;
        #pragma unroll 8
        for (int j = 0; j < R; ++j)
            acc += wbuf[warp*256 + j] * Vs[j*32 + (lane ^ (j & 31))];
        float gate = Gp[(size_t)qr*HC + lane];
        Op[(size_t)qr*HC + lane] = acc*gate;
        __syncwarp();
    }
}

// ---------------------------------------------------------------------------
extern "C" void kernel_launch(void* const* d_in, const int* in_sizes, int n_in,
                              void* d_out, int out_size) {
    const float* msa      = (const float*)d_in[0];
    const float* pair     = (const float*)d_in[1];
    const float* ln_msa_g = (const float*)d_in[2];
    const float* ln_msa_b = (const float*)d_in[3];
    const float* ln_pr_g  = (const float*)d_in[4];
    const float* ln_pr_b  = (const float*)d_in[5];
    const float* w_q      = (const float*)d_in[6];
    const float* w_k      = (const float*)d_in[7];
    const float* w_v      = (const float*)d_in[8];
    const float* w_g      = (const float*)d_in[9];
    const float* b_g      = (const float*)d_in[10];
    const float* w_b      = (const float*)d_in[11];
    const float* b_b      = (const float*)d_in[12];
    const float* w_o      = (const float*)d_in[13];
    const float* b_o      = (const float*)d_in[14];

    float *pm, *pq, *pk, *pv, *pg, *po;
    cudaGetSymbolAddress((void**)&pm, g_m);
    cudaGetSymbolAddress((void**)&pq, g_q);
    cudaGetSymbolAddress((void**)&pk, g_k);
    cudaGetSymbolAddress((void**)&pv, g_v);
    cudaGetSymbolAddress((void**)&pg, g_g);
    cudaGetSymbolAddress((void**)&po, g_o);

    // 1. LayerNorms + pair bias projection
    ln_msa_kernel<<<MROWS, 256>>>(msa, ln_msa_g, ln_msa_b);
    pair_bias_kernel<<<R*R, 128>>>(pair, ln_pr_g, ln_pr_b, w_b, b_b);

    // 2. Q/K/V/G projections ([32768,256] x [256,256])
    dim3 gproj(HC/64, MROWS/128);
    gemm_kernel<0><<<gproj, 256>>>(pm, w_q, nullptr, pq, MROWS, HC, CM);
    gemm_kernel<0><<<gproj, 256>>>(pm, w_k, nullptr, pk, MROWS, HC, CM);
    gemm_kernel<0><<<gproj, 256>>>(pm, w_v, nullptr, pv, MROWS, HC, CM);
    gemm_kernel<2><<<gproj, 256>>>(pm, w_g, b_g, pg, MROWS, HC, CM);

    // 3. Attention (per (s,h) block)
    attn_qk_kernel<<<S*H, 256>>>();
    attn_av_kernel<<<S*H, 256>>>();

    // 4. Output projection + bias -> d_out
    dim3 gout(CM/64, MROWS/128);
    gemm_kernel<1><<<gout, 256>>>(po, w_o, b_o, (float*)d_out, MROWS, CM, HC);
}

// round 2
// speedup vs baseline: 2.0794x; 2.0794x over previous
#include <cuda_runtime.h>
#include <math.h>

// Shapes (fixed per problem)
#define S   128
#define R   256
#define CM  256
#define CZ  128
#define H   8
#define CH  32
#define HC  (H*CH)     // 256
#define MROWS (S*R)    // 32768

// ---------------- device scratch (no allocations allowed) ----------------
__device__ float g_m   [MROWS*CM];   // ln(msa)
__device__ float g_q   [MROWS*HC];
__device__ float g_k   [MROWS*HC];
__device__ float g_v   [MROWS*HC];
__device__ float g_g   [MROWS*HC];   // sigmoid gates
__device__ float g_bias[H*R*R];      // pair bias [h][i][j]
__device__ float g_w   [S*H*R*R];    // logits / softmax weights
__device__ float g_o   [MROWS*HC];   // gated attention output

// ---------------- tf32 helpers ----------------
__device__ __forceinline__ unsigned f2tf(float f) {
    unsigned u;
    asm("cvt.rna.tf32.f32 %0, %1;" : "=r"(u) : "f"(f));
    return u;
}
__device__ __forceinline__ void mma8(float* c, const unsigned* a, const unsigned* b) {
    asm volatile(
        "mma.sync.aligned.m16n8k8.row.col.f32.tf32.tf32.f32 "
        "{%0,%1,%2,%3}, {%4,%5,%6,%7}, {%8,%9}, {%0,%1,%2,%3};"
        : "+f"(c[0]), "+f"(c[1]), "+f"(c[2]), "+f"(c[3])
        : "r"(a[0]), "r"(a[1]), "r"(a[2]), "r"(a[3]), "r"(b[0]), "r"(b[1]));
}

// ---------------- LayerNorm over C_M=256 (one block per row) ----------------
__global__ void ln_msa_kernel(const float* __restrict__ x,
                              const float* __restrict__ gamma,
                              const float* __restrict__ beta) {
    int row = blockIdx.x;
    int t = threadIdx.x;
    float v = x[(size_t)row*CM + t];
    float s1 = v, s2 = v*v;
    #pragma unroll
    for (int o = 16; o; o >>= 1) {
        s1 += __shfl_xor_sync(0xffffffffu, s1, o);
        s2 += __shfl_xor_sync(0xffffffffu, s2, o);
    }
    __shared__ float r1[8], r2[8];
    int w = t >> 5, lane = t & 31;
    if (lane == 0) { r1[w] = s1; r2[w] = s2; }
    __syncthreads();
    float ts1 = 0.f, ts2 = 0.f;
    #pragma unroll
    for (int i = 0; i < 8; ++i) { ts1 += r1[i]; ts2 += r2[i]; }
    float mu  = ts1 * (1.f/CM);
    float var = ts2 * (1.f/CM) - mu*mu;
    float rs  = rsqrtf(var + 1e-5f);
    g_m[(size_t)row*CM + t] = (v - mu)*rs*gamma[t] + beta[t];
}

// ------------- pair LayerNorm (C_Z=128) + project to bias [H,R,R] -------------
__global__ void pair_bias_kernel(const float* __restrict__ z,
                                 const float* __restrict__ gamma,
                                 const float* __restrict__ beta,
                                 const float* __restrict__ wb,
                                 const float* __restrict__ bb) {
    int ij = blockIdx.x;
    int t  = threadIdx.x;             // 0..127
    float v = z[(size_t)ij*CZ + t];
    float s1 = v, s2 = v*v;
    #pragma unroll
    for (int o = 16; o; o >>= 1) {
        s1 += __shfl_xor_sync(0xffffffffu, s1, o);
        s2 += __shfl_xor_sync(0xffffffffu, s2, o);
    }
    __shared__ float r1[4], r2[4];
    int w = t >> 5, lane = t & 31;
    if (lane == 0) { r1[w] = s1; r2[w] = s2; }
    __syncthreads();
    float ts1 = r1[0]+r1[1]+r1[2]+r1[3];
    float ts2 = r2[0]+r2[1]+r2[2]+r2[3];
    float mu  = ts1 * (1.f/CZ);
    float var = ts2 * (1.f/CZ) - mu*mu;
    float rs  = rsqrtf(var + 1e-5f);
    float zn  = (v - mu)*rs*gamma[t] + beta[t];

    __shared__ float part[4][8];
    #pragma unroll
    for (int h = 0; h < H; ++h) {
        float p = zn * wb[t*H + h];
        #pragma unroll
        for (int o = 16; o; o >>= 1) p += __shfl_xor_sync(0xffffffffu, p, o);
        if (lane == 0) part[w][h] = p;
    }
    __syncthreads();
    if (t < H) {
        float sum = part[0][t] + part[1][t] + part[2][t] + part[3][t] + bb[t];
        g_bias[(size_t)t*(R*R) + ij] = sum;
    }
}

// =======================================================================
// TF32 tensor-core GEMM: C[M,N] = A[M,K] @ B[K,N], row-major, 128x128x32
// EPI: 0 = none, 1 = +bias, 2 = sigmoid(x + bias)
// =======================================================================
template<int EPI>
__global__ void gemm_tc(const float* __restrict__ A,
                        const float* __restrict__ B,
                        const float* __restrict__ bias,
                        float* __restrict__ C,
                        int M, int N, int K) {
    __shared__ float As[128*36];   // [m][k], stride 36
    __shared__ float Bs[32*132];   // [k][n], stride 132
    int tid = threadIdx.x;
    int warp = tid >> 5, lane = tid & 31;
    int g = lane >> 2, tg = lane & 3;     // groupID, thread-in-group
    int wm = warp >> 1, wn = warp & 1;    // warp grid 4x2 -> tile 32m x 64n
    int m0 = blockIdx.y * 128, n0 = blockIdx.x * 128;

    float acc[2][8][4];
    #pragma unroll
    for (int mt = 0; mt < 2; ++mt)
        #pragma unroll
        for (int nt = 0; nt < 8; ++nt)
            #pragma unroll
            for (int i = 0; i < 4; ++i) acc[mt][nt][i] = 0.f;

    for (int kt = 0; kt < K; kt += 32) {
        #pragma unroll
        for (int l = 0; l < 4; ++l) {     // A tile: 128x32
            int idx = l*256 + tid;
            int row = idx >> 3, c4 = (idx & 7) * 4;
            *(float4*)(As + row*36 + c4) =
                *(const float4*)(A + (size_t)(m0+row)*K + kt + c4);
        }
        #pragma unroll
        for (int l = 0; l < 4; ++l) {     // B tile: 32x128
            int idx = l*256 + tid;
            int row = idx >> 5, c4 = (idx & 31) * 4;
            *(float4*)(Bs + row*132 + c4) =
                *(const float4*)(B + (size_t)(kt+row)*N + n0 + c4);
        }
        __syncthreads();
        #pragma unroll
        for (int ks = 0; ks < 32; ks += 8) {
            unsigned af[2][4], bf[8][2];
            #pragma unroll
            for (int mt = 0; mt < 2; ++mt) {
                int rb = wm*32 + mt*16;
                af[mt][0] = f2tf(As[(rb+g  )*36 + ks+tg  ]);
                af[mt][1] = f2tf(As[(rb+g+8)*36 + ks+tg  ]);
                af[mt][2] = f2tf(As[(rb+g  )*36 + ks+tg+4]);
                af[mt][3] = f2tf(As[(rb+g+8)*36 + ks+tg+4]);
            }
            #pragma unroll
            for (int nt = 0; nt < 8; ++nt) {
                int col = wn*64 + nt*8 + g;
                bf[nt][0] = f2tf(Bs[(ks+tg  )*132 + col]);
                bf[nt][1] = f2tf(Bs[(ks+tg+4)*132 + col]);
            }
            #pragma unroll
            for (int mt = 0; mt < 2; ++mt)
                #pragma unroll
                for (int nt = 0; nt < 8; ++nt)
                    mma8(acc[mt][nt], af[mt], bf[nt]);
        }
        __syncthreads();
    }

    #pragma unroll
    for (int mt = 0; mt < 2; ++mt) {
        int row0 = m0 + wm*32 + mt*16 + g;
        #pragma unroll
        for (int nt = 0; nt < 8; ++nt) {
            int col = n0 + wn*64 + nt*8 + tg*2;
            float b0 = 0.f, b1 = 0.f;
            if (EPI >= 1) { b0 = bias[col]; b1 = bias[col+1]; }
            #pragma unroll
            for (int half = 0; half < 2; ++half) {
                int row = row0 + half*8;
                float v0 = acc[mt][nt][half*2+0];
                float v1 = acc[mt][nt][half*2+1];
                if (EPI >= 1) { v0 += b0; v1 += b1; }
                if (EPI == 2) {
                    v0 = 1.f/(1.f + __expf(-v0));
                    v1 = 1.f/(1.f + __expf(-v1));
                }
                *(float2*)(C + (size_t)row*N + col) = make_float2(v0, v1);
            }
        }
    }
}

// =======================================================================
// Batched QK^T: logits[sh][q][j] = Q.K/sqrt(C) + bias[h][q][j]
// grid (N/128, M/128, S*H), block tile 128x128, K=32
// =======================================================================
__global__ void qk_tc() {
    __shared__ float As[128*36];   // Q tile [q][d]
    __shared__ float Bs[32*132];   // K^T tile [d][j]
    int tid = threadIdx.x;
    int warp = tid >> 5, lane = tid & 31;
    int g = lane >> 2, tg = lane & 3;
    int wm = warp >> 1, wn = warp & 1;
    int m0 = blockIdx.y * 128, n0 = blockIdx.x * 128;
    int sh = blockIdx.z, s = sh >> 3, h = sh & 7;

    const float* Ab = g_q + (size_t)s*R*HC + h*CH;
    const float* Kb = g_k + (size_t)s*R*HC + h*CH;
    const float* Bb = g_bias + (size_t)h*R*R;
    float* Wp = g_w + (size_t)sh*R*R;

    #pragma unroll
    for (int l = 0; l < 4; ++l) {     // Q tile 128x32
        int idx = l*256 + tid;
        int row = idx >> 3, c4 = (idx & 7) * 4;
        *(float4*)(As + row*36 + c4) =
            *(const float4*)(Ab + (size_t)(m0+row)*HC + c4);
    }
    #pragma unroll
    for (int l = 0; l < 4; ++l) {     // K tile 128x32 -> transpose into Bs[d][j]
        int idx = l*256 + tid;
        int j = idx >> 3, d4 = (idx & 7) * 4;
        float4 kv = *(const float4*)(Kb + (size_t)(n0+j)*HC + d4);
        Bs[(d4+0)*132 + j] = kv.x;
        Bs[(d4+1)*132 + j] = kv.y;
        Bs[(d4+2)*132 + j] = kv.z;
        Bs[(d4+3)*132 + j] = kv.w;
    }
    __syncthreads();

    float acc[2][8][4];
    #pragma unroll
    for (int mt = 0; mt < 2; ++mt)
        #pragma unroll
        for (int nt = 0; nt < 8; ++nt)
            #pragma unroll
            for (int i = 0; i < 4; ++i) acc[mt][nt][i] = 0.f;

    #pragma unroll
    for (int ks = 0; ks < 32; ks += 8) {
        unsigned af[2][4], bf[8][2];
        #pragma unroll
        for (int mt = 0; mt < 2; ++mt) {
            int rb = wm*32 + mt*16;
            af[mt][0] = f2tf(As[(rb+g  )*36 + ks+tg  ]);
            af[mt][1] = f2tf(As[(rb+g+8)*36 + ks+tg  ]);
            af[mt][2] = f2tf(As[(rb+g  )*36 + ks+tg+4]);
            af[mt][3] = f2tf(As[(rb+g+8)*36 + ks+tg+4]);
        }
        #pragma unroll
        for (int nt = 0; nt < 8; ++nt) {
            int col = wn*64 + nt*8 + g;
            bf[nt][0] = f2tf(Bs[(ks+tg  )*132 + col]);
            bf[nt][1] = f2tf(Bs[(ks+tg+4)*132 + col]);
        }
        #pragma unroll
        for (int mt = 0; mt < 2; ++mt)
            #pragma unroll
            for (int nt = 0; nt < 8; ++nt)
                mma8(acc[mt][nt], af[mt], bf[nt]);
    }

    const float sc = 0.17677669529663687f;   // 1/sqrt(32)
    #pragma unroll
    for (int mt = 0; mt < 2; ++mt) {
        int row0 = m0 + wm*32 + mt*16 + g;
        #pragma unroll
        for (int nt = 0; nt < 8; ++nt) {
            int col = n0 + wn*64 + nt*8 + tg*2;
            #pragma unroll
            for (int half = 0; half < 2; ++half) {
                int row = row0 + half*8;
                float2 bb = *(const float2*)(Bb + (size_t)row*R + col);
                float v0 = acc[mt][nt][half*2+0]*sc + bb.x;
                float v1 = acc[mt][nt][half*2+1]*sc + bb.y;
                *(float2*)(Wp + (size_t)row*R + col) = make_float2(v0, v1);
            }
        }
    }
}

// ---------------- row softmax over 256, in place on g_w ----------------
__global__ void softmax_kernel() {
    int warp = threadIdx.x >> 5, lane = threadIdx.x & 31;
    size_t row = (size_t)blockIdx.x*8 + warp;
    float* p = g_w + row*R;
    float v[8];
    float mx = -1e30f;
    #pragma unroll
    for (int i = 0; i < 8; ++i) { v[i] = p[i*32 + lane]; mx = fmaxf(mx, v[i]); }
    #pragma unroll
    for (int o = 16; o; o >>= 1) mx = fmaxf(mx, __shfl_xor_sync(0xffffffffu, mx, o));
    float sum = 0.f;
    #pragma unroll
    for (int i = 0; i < 8; ++i) { v[i] = __expf(v[i] - mx); sum += v[i]; }
    #pragma unroll
    for (int o = 16; o; o >>= 1) sum += __shfl_xor_sync(0xffffffffu, sum, o);
    float inv = 1.f/sum;
    #pragma unroll
    for (int i = 0; i < 8; ++i) p[i*32 + lane] = v[i]*inv;
}

// =======================================================================
// Batched AV + gate: O[q][d] = gate[q][d] * sum_j W[q][j] V[j][d]
// one block per (s,h); M=256, N=32, K=256 chunked by 32
// =======================================================================
__global__ void av_tc() {
    __shared__ float As[256*36];   // W tile [q][j]
    __shared__ float Bs[32*36];    // V tile [j][d]
    int tid = threadIdx.x;
    int warp = tid >> 5, lane = tid & 31;
    int g = lane >> 2, tg = lane & 3;
    int sh = blockIdx.x, s = sh >> 3, h = sh & 7;

    const float* Wb = g_w + (size_t)sh*R*R;
    const float* Vb = g_v + (size_t)s*R*HC + h*CH;
    const float* Gb = g_g + (size_t)s*R*HC + h*CH;
    float* Ob = g_o + (size_t)s*R*HC + h*CH;

    float acc[2][4][4];
    #pragma unroll
    for (int mt = 0; mt < 2; ++mt)
        #pragma unroll
        for (int nt = 0; nt < 4; ++nt)
            #pragma unroll
            for (int i = 0; i < 4; ++i) acc[mt][nt][i] = 0.f;

    for (int jt = 0; jt < R; jt += 32) {
        #pragma unroll
        for (int l = 0; l < 8; ++l) {     // W tile 256x32
            int idx = l*256 + tid;
            int row = idx >> 3, c4 = (idx & 7) * 4;
            *(float4*)(As + row*36 + c4) =
                *(const float4*)(Wb + (size_t)row*R + jt + c4);
        }
        {                                  // V tile 32x32
            int j = tid >> 3, d4 = (tid & 7) * 4;
            *(float4*)(Bs + j*36 + d4) =
                *(const float4*)(Vb + (size_t)(jt+j)*HC + d4);
        }
        __syncthreads();
        #pragma unroll
        for (int ks = 0; ks < 32; ks += 8) {
            unsigned af[2][4], bf[4][2];
            #pragma unroll
            for (int mt = 0; mt < 2; ++mt) {
                int rb = warp*32 + mt*16;
                af[mt][0] = f2tf(As[(rb+g  )*36 + ks+tg  ]);
                af[mt][1] = f2tf(As[(rb+g+8)*36 + ks+tg  ]);
                af[mt][2] = f2tf(As[(rb+g  )*36 + ks+tg+4]);
                af[mt][3] = f2tf(As[(rb+g+8)*36 + ks+tg+4]);
            }
            #pragma unroll
            for (int nt = 0; nt < 4; ++nt) {
                int col = nt*8 + g;
                bf[nt][0] = f2tf(Bs[(ks+tg  )*36 + col]);
                bf[nt][1] = f2tf(Bs[(ks+tg+4)*36 + col]);
            }
            #pragma unroll
            for (int mt = 0; mt < 2; ++mt)
                #pragma unroll
                for (int nt = 0; nt < 4; ++nt)
                    mma8(acc[mt][nt], af[mt], bf[nt]);
        }
        __syncthreads();
    }

    #pragma unroll
    for (int mt = 0; mt < 2; ++mt) {
        int row0 = warp*32 + mt*16 + g;
        #pragma unroll
        for (int nt = 0; nt < 4; ++nt) {
            int col = nt*8 + tg*2;
            #pragma unroll
            for (int half = 0; half < 2; ++half) {
                int row = row0 + half*8;
                float2 gt = *(const float2*)(Gb + (size_t)row*HC + col);
                float v0 = acc[mt][nt][half*2+0] * gt.x;
                float v1 = acc[mt][nt][half*2+1] * gt.y;
                *(float2*)(Ob + (size_t)row*HC + col) = make_float2(v0, v1);
            }
        }
    }
}

// ---------------------------------------------------------------------------
extern "C" void kernel_launch(void* const* d_in, const int* in_sizes, int n_in,
                              void* d_out, int out_size) {
    const float* msa      = (const float*)d_in[0];
    const float* pair     = (const float*)d_in[1];
    const float* ln_msa_g = (const float*)d_in[2];
    const float* ln_msa_b = (const float*)d_in[3];
    const float* ln_pr_g  = (const float*)d_in[4];
    const float* ln_pr_b  = (const float*)d_in[5];
    const float* w_q      = (const float*)d_in[6];
    const float* w_k      = (const float*)d_in[7];
    const float* w_v      = (const float*)d_in[8];
    const float* w_g      = (const float*)d_in[9];
    const float* b_g      = (const float*)d_in[10];
    const float* w_b      = (const float*)d_in[11];
    const float* b_b      = (const float*)d_in[12];
    const float* w_o      = (const float*)d_in[13];
    const float* b_o      = (const float*)d_in[14];

    float *pm, *pq, *pk, *pv, *pg, *po;
    cudaGetSymbolAddress((void**)&pm, g_m);
    cudaGetSymbolAddress((void**)&pq, g_q);
    cudaGetSymbolAddress((void**)&pk, g_k);
    cudaGetSymbolAddress((void**)&pv, g_v);
    cudaGetSymbolAddress((void**)&pg, g_g);
    cudaGetSymbolAddress((void**)&po, g_o);

    // 1. LayerNorms + pair bias projection
    ln_msa_kernel<<<MROWS, 256>>>(msa, ln_msa_g, ln_msa_b);
    pair_bias_kernel<<<R*R, 128>>>(pair, ln_pr_g, ln_pr_b, w_b, b_b);

    // 2. Q/K/V/G projections ([32768,256] x [256,256]) on tensor cores
    dim3 gproj(HC/128, MROWS/128);
    gemm_tc<0><<<gproj, 256>>>(pm, w_q, nullptr, pq, MROWS, HC, CM);
    gemm_tc<0><<<gproj, 256>>>(pm, w_k, nullptr, pk, MROWS, HC, CM);
    gemm_tc<0><<<gproj, 256>>>(pm, w_v, nullptr, pv, MROWS, HC, CM);
    gemm_tc<2><<<gproj, 256>>>(pm, w_g, b_g, pg, MROWS, HC, CM);

    // 3. Attention: QK^T+bias -> softmax -> AV*gate
    dim3 gqk(R/128, R/128, S*H);
    qk_tc<<<gqk, 256>>>();
    softmax_kernel<<<S*H*R/8, 256>>>();
    av_tc<<<S*H, 256>>>();

    // 4. Output projection + bias -> d_out
    dim3 gout(CM/128, MROWS/128);
    gemm_tc<1><<<gout, 256>>>(po, w_o, b_o, (float*)d_out, MROWS, CM, HC);
}

// round 3
// speedup vs baseline: 2.6298x; 1.2647x over previous
#include <cuda_runtime.h>
#include <cuda_fp16.h>
#include <math.h>

#define S   128
#define R   256
#define CM  256
#define CZ  128
#define H   8
#define CH  32
#define HC  256
#define MROWS 32768

// ---------------- device scratch ----------------
__device__ float g_m [MROWS*CM];
__device__ float g_q [MROWS*HC];
__device__ float g_k [MROWS*HC];
__device__ float g_v [MROWS*HC];
__device__ float g_g [MROWS*HC];
__device__ float g_o [MROWS*HC];
__device__ float g_bias[H*R*R];
__device__ __half g_wh[(size_t)S*H*R*R];      // softmax weights, fp16
__device__ float g_wts[5][CM*HC];             // tf32-rounded weights: q,k,v,g,o

// ---------------- helpers ----------------
__device__ __forceinline__ unsigned f2tf(float f) {
    unsigned u;
    asm("cvt.rna.tf32.f32 %0, %1;" : "=r"(u) : "f"(f));
    return u;
}
__device__ __forceinline__ float tfr(float f) { return __uint_as_float(f2tf(f)); }
__device__ __forceinline__ unsigned fu(float f) { return __float_as_uint(f); }

__device__ __forceinline__ void mma8(float* c, const unsigned* a, const unsigned* b) {
    asm volatile(
        "mma.sync.aligned.m16n8k8.row.col.f32.tf32.tf32.f32 "
        "{%0,%1,%2,%3}, {%4,%5,%6,%7}, {%8,%9}, {%0,%1,%2,%3};"
        : "+f"(c[0]), "+f"(c[1]), "+f"(c[2]), "+f"(c[3])
        : "r"(a[0]), "r"(a[1]), "r"(a[2]), "r"(a[3]), "r"(b[0]), "r"(b[1]));
}
__device__ __forceinline__ void mma16h(float* c, const unsigned* a, const unsigned* b) {
    asm volatile(
        "mma.sync.aligned.m16n8k16.row.col.f32.f16.f16.f32 "
        "{%0,%1,%2,%3}, {%4,%5,%6,%7}, {%8,%9}, {%0,%1,%2,%3};"
        : "+f"(c[0]), "+f"(c[1]), "+f"(c[2]), "+f"(c[3])
        : "r"(a[0]), "r"(a[1]), "r"(a[2]), "r"(a[3]), "r"(b[0]), "r"(b[1]));
}
__device__ __forceinline__ unsigned sptr(const void* p) {
    return (unsigned)__cvta_generic_to_shared(p);
}
#define CP16(dst, src) asm volatile("cp.async.ca.shared.global [%0], [%1], 16;" :: "r"(dst), "l"(src) : "memory")
#define CP_COMMIT()    asm volatile("cp.async.commit_group;" ::: "memory")
#define CP_WAIT0()     asm volatile("cp.async.wait_group 0;" ::: "memory")
#define CP_WAIT1()     asm volatile("cp.async.wait_group 1;" ::: "memory")

// ---------------- weight pre-rounding (tf32) ----------------
__global__ void round_w(const float* __restrict__ a0, const float* __restrict__ a1,
                        const float* __restrict__ a2, const float* __restrict__ a3,
                        const float* __restrict__ a4) {
    int i = blockIdx.x*256 + threadIdx.x;     // grid 1280 -> 5*65536
    int m = i >> 16, j = i & 65535;
    const float* src = (m==0)?a0:(m==1)?a1:(m==2)?a2:(m==3)?a3:a4;
    g_wts[m][j] = tfr(src[j]);
}

// ---------------- LayerNorm over C_M=256 (tf32-rounded output) ----------------
__global__ void ln_msa_kernel(const float* __restrict__ x,
                              const float* __restrict__ gamma,
                              const float* __restrict__ beta) {
    int row = blockIdx.x;
    int t = threadIdx.x;
    float v = x[(size_t)row*CM + t];
    float s1 = v, s2 = v*v;
    #pragma unroll
    for (int o = 16; o; o >>= 1) {
        s1 += __shfl_xor_sync(0xffffffffu, s1, o);
        s2 += __shfl_xor_sync(0xffffffffu, s2, o);
    }
    __shared__ float r1[8], r2[8];
    int w = t >> 5, lane = t & 31;
    if (lane == 0) { r1[w] = s1; r2[w] = s2; }
    __syncthreads();
    float ts1 = 0.f, ts2 = 0.f;
    #pragma unroll
    for (int i = 0; i < 8; ++i) { ts1 += r1[i]; ts2 += r2[i]; }
    float mu  = ts1 * (1.f/CM);
    float var = ts2 * (1.f/CM) - mu*mu;
    float rs  = rsqrtf(var + 1e-5f);
    g_m[(size_t)row*CM + t] = tfr((v - mu)*rs*gamma[t] + beta[t]);
}

// ---------------- pair LN + bias projection ----------------
__global__ void pair_bias_kernel(const float* __restrict__ z,
                                 const float* __restrict__ gamma,
                                 const float* __restrict__ beta,
                                 const float* __restrict__ wb,
                                 const float* __restrict__ bb) {
    int ij = blockIdx.x;
    int t  = threadIdx.x;             // 0..127
    float v = z[(size_t)ij*CZ + t];
    float s1 = v, s2 = v*v;
    #pragma unroll
    for (int o = 16; o; o >>= 1) {
        s1 += __shfl_xor_sync(0xffffffffu, s1, o);
        s2 += __shfl_xor_sync(0xffffffffu, s2, o);
    }
    __shared__ float r1[4], r2[4];
    int w = t >> 5, lane = t & 31;
    if (lane == 0) { r1[w] = s1; r2[w] = s2; }
    __syncthreads();
    float ts1 = r1[0]+r1[1]+r1[2]+r1[3];
    float ts2 = r2[0]+r2[1]+r2[2]+r2[3];
    float mu  = ts1 * (1.f/CZ);
    float var = ts2 * (1.f/CZ) - mu*mu;
    float rs  = rsqrtf(var + 1e-5f);
    float zn  = (v - mu)*rs*gamma[t] + beta[t];

    __shared__ float part[4][8];
    #pragma unroll
    for (int h = 0; h < H; ++h) {
        float p = zn * wb[t*H + h];
        #pragma unroll
        for (int o = 16; o; o >>= 1) p += __shfl_xor_sync(0xffffffffu, p, o);
        if (lane == 0) part[w][h] = p;
    }
    __syncthreads();
    if (t < H) {
        float sum = part[0][t] + part[1][t] + part[2][t] + part[3][t] + bb[t];
        g_bias[(size_t)t*(R*R) + ij] = sum;
    }
}

// =======================================================================
// TF32 GEMM, cp.async 2-stage, BM=128 BN=128 BK=16, 256 thr, warp 32x64
// EPI: 0 = tf32-rounded store, 1 = +bias, 2 = sigmoid(x+bias)
// Inputs assumed pre-rounded to tf32 values.
// =======================================================================
template<int EPI>
__global__ __launch_bounds__(256) void gemm2(const float* __restrict__ A,
                                             const float* __restrict__ B,
                                             const float* __restrict__ bias,
                                             float* __restrict__ C,
                                             int N, int K) {
    __shared__ __align__(16) float As[2][128*20];
    __shared__ __align__(16) float Bs[2][16*136];
    int tid = threadIdx.x, warp = tid >> 5, lane = tid & 31;
    int g = lane >> 2, tg = lane & 3;
    int wm = warp >> 1, wn = warp & 1;
    int m0 = blockIdx.y * 128, n0 = blockIdx.x * 128;
    int nk = K >> 4;

    float acc[2][8][4];
    #pragma unroll
    for (int mt = 0; mt < 2; ++mt)
        #pragma unroll
        for (int nt = 0; nt < 8; ++nt)
            #pragma unroll
            for (int i = 0; i < 4; ++i) acc[mt][nt][i] = 0.f;

    // stage issue
    #define ISSUE(kt, st) {                                                     \
        const float* Ab = A + (size_t)m0*K + (kt)*16;                           \
        _Pragma("unroll")                                                       \
        for (int l = 0; l < 2; ++l) {                                           \
            int idx = l*256 + tid; int row = idx >> 2, c4 = (idx & 3)*4;        \
            CP16(sptr(&As[st][row*20 + c4]), Ab + (size_t)row*K + c4);          \
        }                                                                       \
        const float* Bb2 = B + (size_t)((kt)*16)*N + n0;                        \
        _Pragma("unroll")                                                       \
        for (int l = 0; l < 2; ++l) {                                           \
            int idx = l*256 + tid; int row = idx >> 5, c4 = (idx & 31)*4;       \
            CP16(sptr(&Bs[st][row*136 + c4]), Bb2 + (size_t)row*N + c4);        \
        }                                                                       \
        CP_COMMIT();                                                            \
    }

    ISSUE(0, 0);
    for (int kt = 0; kt < nk; ++kt) {
        if (kt + 1 < nk) { ISSUE(kt+1, (kt+1)&1); CP_WAIT1(); }
        else CP_WAIT0();
        __syncthreads();
        int st = kt & 1;
        #pragma unroll
        for (int ks = 0; ks < 16; ks += 8) {
            unsigned af[2][4], bf[8][2];
            #pragma unroll
            for (int mt = 0; mt < 2; ++mt) {
                int rb = wm*32 + mt*16;
                af[mt][0] = fu(As[st][(rb+g  )*20 + ks+tg  ]);
                af[mt][1] = fu(As[st][(rb+g+8)*20 + ks+tg  ]);
                af[mt][2] = fu(As[st][(rb+g  )*20 + ks+tg+4]);
                af[mt][3] = fu(As[st][(rb+g+8)*20 + ks+tg+4]);
            }
            #pragma unroll
            for (int nt = 0; nt < 8; ++nt) {
                int col = wn*64 + nt*8 + g;
                bf[nt][0] = fu(Bs[st][(ks+tg  )*136 + col]);
                bf[nt][1] = fu(Bs[st][(ks+tg+4)*136 + col]);
            }
            #pragma unroll
            for (int mt = 0; mt < 2; ++mt)
                #pragma unroll
                for (int nt = 0; nt < 8; ++nt)
                    mma8(acc[mt][nt], af[mt], bf[nt]);
        }
        __syncthreads();
    }
    #undef ISSUE

    #pragma unroll
    for (int mt = 0; mt < 2; ++mt) {
        int row0 = m0 + wm*32 + mt*16 + g;
        #pragma unroll
        for (int nt = 0; nt < 8; ++nt) {
            int col = n0 + wn*64 + nt*8 + tg*2;
            float b0 = 0.f, b1 = 0.f;
            if (EPI >= 1) { b0 = bias[col]; b1 = bias[col+1]; }
            #pragma unroll
            for (int half = 0; half < 2; ++half) {
                int row = row0 + half*8;
                float v0 = acc[mt][nt][half*2+0];
                float v1 = acc[mt][nt][half*2+1];
                if (EPI >= 1) { v0 += b0; v1 += b1; }
                if (EPI == 2) {
                    v0 = 1.f/(1.f + __expf(-v0));
                    v1 = 1.f/(1.f + __expf(-v1));
                }
                if (EPI == 0) { v0 = tfr(v0); v1 = tfr(v1); }
                *(float2*)(C + (size_t)row*N + col) = make_float2(v0, v1);
            }
        }
    }
}

// =======================================================================
// Fused QK^T + bias + softmax -> g_wh (fp16)
// block = 64 q-rows x full 256 cols, grid = S*H*4
// =======================================================================
__global__ __launch_bounds__(256) void qk_softmax() {
    __shared__ __align__(16) float Qs[64*36];
    __shared__ __align__(16) float Ks[256*36];
    __shared__ float redm[64][2], reds[64][2];
    int b = blockIdx.x;
    int sh = b >> 2, m0 = (b & 3)*64;
    int s = sh >> 3, h = sh & 7;
    int tid = threadIdx.x, warp = tid >> 5, lane = tid & 31;
    int g = lane >> 2, tg = lane & 3;
    int wm = warp >> 1, wn = warp & 1;

    const float* Qp = g_q + (size_t)s*R*HC + h*CH;
    const float* Kp = g_k + (size_t)s*R*HC + h*CH;

    #pragma unroll
    for (int l = 0; l < 2; ++l) {               // Q: 64x32
        int idx = l*256 + tid; int row = idx >> 3, c4 = (idx & 7)*4;
        CP16(sptr(&Qs[row*36 + c4]), Qp + (size_t)(m0+row)*HC + c4);
    }
    #pragma unroll
    for (int l = 0; l < 8; ++l) {               // K: 256x32
        int idx = l*256 + tid; int row = idx >> 3, c4 = (idx & 7)*4;
        CP16(sptr(&Ks[row*36 + c4]), Kp + (size_t)row*HC + c4);
    }
    CP_COMMIT(); CP_WAIT0();
    __syncthreads();

    float acc[16][4];
    #pragma unroll
    for (int nt = 0; nt < 16; ++nt)
        #pragma unroll
        for (int i = 0; i < 4; ++i) acc[nt][i] = 0.f;

    int rb = wm*16;
    #pragma unroll
    for (int ks = 0; ks < 32; ks += 8) {
        unsigned af[4];
        af[0] = fu(Qs[(rb+g  )*36 + ks+tg  ]);
        af[1] = fu(Qs[(rb+g+8)*36 + ks+tg  ]);
        af[2] = fu(Qs[(rb+g  )*36 + ks+tg+4]);
        af[3] = fu(Qs[(rb+g+8)*36 + ks+tg+4]);
        #pragma unroll
        for (int nt = 0; nt < 16; ++nt) {
            int col = wn*128 + nt*8 + g;
            unsigned bf[2] = { fu(Ks[col*36 + ks+tg]), fu(Ks[col*36 + ks+tg+4]) };
            mma8(acc[nt], af, bf);
        }
    }

    const float sc = 0.17677669529663687f;   // 1/sqrt(32)
    int rA = rb + g, rB = rb + g + 8;        // local row ids (0..63)
    const float* Bb = g_bias + (size_t)h*R*R + (size_t)m0*R;
    float mxA = -1e30f, mxB = -1e30f;
    #pragma unroll
    for (int nt = 0; nt < 16; ++nt) {
        int col = wn*128 + nt*8 + tg*2;
        float2 bA = *(const float2*)(Bb + (size_t)rA*R + col);
        float2 bB = *(const float2*)(Bb + (size_t)rB*R + col);
        acc[nt][0] = fmaf(acc[nt][0], sc, bA.x);
        acc[nt][1] = fmaf(acc[nt][1], sc, bA.y);
        acc[nt][2] = fmaf(acc[nt][2], sc, bB.x);
        acc[nt][3] = fmaf(acc[nt][3], sc, bB.y);
        mxA = fmaxf(mxA, fmaxf(acc[nt][0], acc[nt][1]));
        mxB = fmaxf(mxB, fmaxf(acc[nt][2], acc[nt][3]));
    }
    mxA = fmaxf(mxA, __shfl_xor_sync(0xffffffffu, mxA, 1));
    mxA = fmaxf(mxA, __shfl_xor_sync(0xffffffffu, mxA, 2));
    mxB = fmaxf(mxB, __shfl_xor_sync(0xffffffffu, mxB, 1));
    mxB = fmaxf(mxB, __shfl_xor_sync(0xffffffffu, mxB, 2));
    if (tg == 0) { redm[rA][wn] = mxA; redm[rB][wn] = mxB; }
    __syncthreads();
    float gA = fmaxf(redm[rA][0], redm[rA][1]);
    float gB = fmaxf(redm[rB][0], redm[rB][1]);

    float sA = 0.f, sB = 0.f;
    #pragma unroll
    for (int nt = 0; nt < 16; ++nt) {
        acc[nt][0] = __expf(acc[nt][0] - gA);
        acc[nt][1] = __expf(acc[nt][1] - gA);
        acc[nt][2] = __expf(acc[nt][2] - gB);
        acc[nt][3] = __expf(acc[nt][3] - gB);
        sA += acc[nt][0] + acc[nt][1];
        sB += acc[nt][2] + acc[nt][3];
    }
    sA += __shfl_xor_sync(0xffffffffu, sA, 1);
    sA += __shfl_xor_sync(0xffffffffu, sA, 2);
    sB += __shfl_xor_sync(0xffffffffu, sB, 1);
    sB += __shfl_xor_sync(0xffffffffu, sB, 2);
    if (tg == 0) { reds[rA][wn] = sA; reds[rB][wn] = sB; }
    __syncthreads();
    float iA = 1.f/(reds[rA][0] + reds[rA][1]);
    float iB = 1.f/(reds[rB][0] + reds[rB][1]);

    __half* Wp = g_wh + (size_t)sh*R*R + (size_t)m0*R;
    #pragma unroll
    for (int nt = 0; nt < 16; ++nt) {
        int col = wn*128 + nt*8 + tg*2;
        *(half2*)(Wp + (size_t)rA*R + col) = __floats2half2_rn(acc[nt][0]*iA, acc[nt][1]*iA);
        *(half2*)(Wp + (size_t)rB*R + col) = __floats2half2_rn(acc[nt][2]*iB, acc[nt][3]*iB);
    }
}

// =======================================================================
// AV (fp16 MMA) + gate: block = 128 q-rows x 32 d, K=256 in 8 chunks
// grid = S*H*2
// =======================================================================
__global__ __launch_bounds__(256) void av_f16() {
    __shared__ __align__(16) __half Ws[2][128*40];
    __shared__ __align__(16) __half Vt[32*264];     // [d][j] transposed
    int b = blockIdx.x;
    int sh = b >> 1, m0 = (b & 1)*128;
    int s = sh >> 3, h = sh & 7;
    int tid = threadIdx.x, warp = tid >> 5, lane = tid & 31;
    int g = lane >> 2, tg = lane & 3;

    const __half* Wb = g_wh + (size_t)sh*R*R;
    const float*  Vp = g_v  + (size_t)s*R*HC + h*CH;

    #define ISSUEW(jt, st) {                                                        \
        _Pragma("unroll")                                                           \
        for (int l = 0; l < 2; ++l) {                                               \
            int idx = l*256 + tid; int row = idx >> 2, c8 = (idx & 3)*8;            \
            CP16(sptr(&Ws[st][row*40 + c8]), Wb + (size_t)(m0+row)*R + (jt) + c8);  \
        }                                                                           \
        CP_COMMIT();                                                                \
    }

    ISSUEW(0, 0);
    // load + transpose + convert V: [j][d] fp32 -> Vt[d][j] fp16
    #pragma unroll
    for (int l = 0; l < 8; ++l) {
        int idx = l*256 + tid;        // 0..2047 float4s
        int j = idx >> 3, d4 = (idx & 7)*4;
        float4 v = *(const float4*)(Vp + (size_t)j*HC + d4);
        Vt[(d4+0)*264 + j] = __float2half_rn(v.x);
        Vt[(d4+1)*264 + j] = __float2half_rn(v.y);
        Vt[(d4+2)*264 + j] = __float2half_rn(v.z);
        Vt[(d4+3)*264 + j] = __float2half_rn(v.w);
    }

    float acc[4][4];
    #pragma unroll
    for (int nt = 0; nt < 4; ++nt)
        #pragma unroll
        for (int i = 0; i < 4; ++i) acc[nt][i] = 0.f;

    int rb = warp*16;
    for (int c = 0; c < 8; ++c) {
        if (c + 1 < 8) { ISSUEW((c+1)*32, (c+1)&1); CP_WAIT1(); }
        else CP_WAIT0();
        __syncthreads();
        int st = c & 1;
        #pragma unroll
        for (int ks = 0; ks < 32; ks += 16) {
            unsigned af[4];
            af[0] = *(const unsigned*)&Ws[st][(rb+g  )*40 + ks + 2*tg    ];
            af[1] = *(const unsigned*)&Ws[st][(rb+g+8)*40 + ks + 2*tg    ];
            af[2] = *(const unsigned*)&Ws[st][(rb+g  )*40 + ks + 2*tg + 8];
            af[3] = *(const unsigned*)&Ws[st][(rb+g+8)*40 + ks + 2*tg + 8];
            int jb = c*32 + ks;
            #pragma unroll
            for (int nt = 0; nt < 4; ++nt) {
                int d = nt*8 + g;
                unsigned bf[2] = {
                    *(const unsigned*)&Vt[d*264 + jb + 2*tg    ],
                    *(const unsigned*)&Vt[d*264 + jb + 2*tg + 8]
                };
                mma16h(acc[nt], af, bf);
            }
        }
        __syncthreads();
    }
    #undef ISSUEW

    const float* Gp = g_g + (size_t)s*R*HC + h*CH;
    float*       Op = g_o + (size_t)s*R*HC + h*CH;
    #pragma unroll
    for (int nt = 0; nt < 4; ++nt) {
        int col = nt*8 + tg*2;
        #pragma unroll
        for (int half = 0; half < 2; ++half) {
            int row = m0 + rb + g + half*8;
            float2 gt = *(const float2*)(Gp + (size_t)row*HC + col);
            float v0 = tfr(acc[nt][half*2+0] * gt.x);
            float v1 = tfr(acc[nt][half*2+1] * gt.y);
            *(float2*)(Op + (size_t)row*HC + col) = make_float2(v0, v1);
        }
    }
}

// ---------------------------------------------------------------------------
extern "C" void kernel_launch(void* const* d_in, const int* in_sizes, int n_in,
                              void* d_out, int out_size) {
    const float* msa      = (const float*)d_in[0];
    const float* pair     = (const float*)d_in[1];
    const float* ln_msa_g = (const float*)d_in[2];
    const float* ln_msa_b = (const float*)d_in[3];
    const float* ln_pr_g  = (const float*)d_in[4];
    const float* ln_pr_b  = (const float*)d_in[5];
    const float* w_q      = (const float*)d_in[6];
    const float* w_k      = (const float*)d_in[7];
    const float* w_v      = (const float*)d_in[8];
    const float* w_g      = (const float*)d_in[9];
    const float* b_g      = (const float*)d_in[10];
    const float* w_b      = (const float*)d_in[11];
    const float* b_b      = (const float*)d_in[12];
    const float* w_o      = (const float*)d_in[13];
    const float* b_o      = (const float*)d_in[14];

    float *pm, *pq, *pk, *pv, *pg, *po, *pw;
    cudaGetSymbolAddress((void**)&pm, g_m);
    cudaGetSymbolAddress((void**)&pq, g_q);
    cudaGetSymbolAddress((void**)&pk, g_k);
    cudaGetSymbolAddress((void**)&pv, g_v);
    cudaGetSymbolAddress((void**)&pg, g_g);
    cudaGetSymbolAddress((void**)&po, g_o);
    cudaGetSymbolAddress((void**)&pw, g_wts);

    // 1. pre-round weights, LayerNorms, pair bias
    round_w<<<1280, 256>>>(w_q, w_k, w_v, w_g, w_o);
    ln_msa_kernel<<<MROWS, 256>>>(msa, ln_msa_g, ln_msa_b);
    pair_bias_kernel<<<R*R, 128>>>(pair, ln_pr_g, ln_pr_b, w_b, b_b);

    // 2. projections
    dim3 gp(2, 256);
    gemm2<0><<<gp, 256>>>(pm, pw + 0*65536, nullptr, pq, HC, CM);
    gemm2<0><<<gp, 256>>>(pm, pw + 1*65536, nullptr, pk, HC, CM);
    gemm2<0><<<gp, 256>>>(pm, pw + 2*65536, nullptr, pv, HC, CM);
    gemm2<2><<<gp, 256>>>(pm, pw + 3*65536, b_g,     pg, HC, CM);

    // 3. attention
    qk_softmax<<<S*H*4, 256>>>();
    av_f16<<<S*H*2, 256>>>();

    // 4. output projection
    gemm2<1><<<gp, 256>>>(po, pw + 4*65536, b_o, (float*)d_out, CM, HC);
}

// round 4
// speedup vs baseline: 3.9110x; 1.4872x over previous
#include <cuda_runtime.h>
#include <cuda_fp16.h>
#include <math.h>

#define S   128
#define R   256
#define CM  256
#define CZ  128
#define H   8
#define CH  32
#define MROWS 32768

// ---------------- device scratch ----------------
__device__ __half g_mh[MROWS*CM];      // ln(msa), fp16
__device__ __half g_qh[MROWS*256];
__device__ __half g_kh[MROWS*256];
__device__ __half g_vh[MROWS*256];
__device__ __half g_oh[MROWS*256];     // gated attention out, fp16
__device__ float  g_g [MROWS*256];     // sigmoid gates, fp32
__device__ float  g_bias[H*R*R];       // pair bias
__device__ __half g_wt[5*256*256];     // packed transposed fp16 weights q,k,v,g,o

// ---------------- helpers ----------------
__device__ __forceinline__ unsigned sptr(const void* p) {
    return (unsigned)__cvta_generic_to_shared(p);
}
#define CP16(dst, src) asm volatile("cp.async.ca.shared.global [%0], [%1], 16;" :: "r"(dst), "l"(src) : "memory")
#define CP_COMMIT()    asm volatile("cp.async.commit_group;" ::: "memory")
#define CP_WAIT0()     asm volatile("cp.async.wait_group 0;" ::: "memory")
#define CP_WAIT1()     asm volatile("cp.async.wait_group 1;" ::: "memory")

__device__ __forceinline__ void ldsm_x4(unsigned* r, unsigned a) {
    asm volatile("ldmatrix.sync.aligned.m8n8.x4.shared.b16 {%0,%1,%2,%3}, [%4];"
        : "=r"(r[0]),"=r"(r[1]),"=r"(r[2]),"=r"(r[3]) : "r"(a));
}
__device__ __forceinline__ void ldsm_x4t(unsigned* r, unsigned a) {
    asm volatile("ldmatrix.sync.aligned.m8n8.x4.trans.shared.b16 {%0,%1,%2,%3}, [%4];"
        : "=r"(r[0]),"=r"(r[1]),"=r"(r[2]),"=r"(r[3]) : "r"(a));
}
__device__ __forceinline__ void mma16h(float* c, const unsigned* a, const unsigned* b) {
    asm volatile(
        "mma.sync.aligned.m16n8k16.row.col.f32.f16.f16.f32 "
        "{%0,%1,%2,%3}, {%4,%5,%6,%7}, {%8,%9}, {%0,%1,%2,%3};"
        : "+f"(c[0]), "+f"(c[1]), "+f"(c[2]), "+f"(c[3])
        : "r"(a[0]), "r"(a[1]), "r"(a[2]), "r"(a[3]), "r"(b[0]), "r"(b[1]));
}
__device__ __forceinline__ unsigned pk2(float a, float b) {
    __half2 h = __floats2half2_rn(a, b);
    return *reinterpret_cast<unsigned*>(&h);
}

// ---------------- pack weights: fp16, transposed [n][k] ----------------
__global__ void pack_w(const float* __restrict__ a0, const float* __restrict__ a1,
                       const float* __restrict__ a2, const float* __restrict__ a3,
                       const float* __restrict__ a4) {
    int i = blockIdx.x*256 + threadIdx.x;     // 5 * 65536
    int m = i >> 16, rem = i & 65535;
    int n = rem & 255, k = rem >> 8;
    const float* src = (m==0)?a0:(m==1)?a1:(m==2)?a2:(m==3)?a3:a4;
    g_wt[(size_t)m*65536 + n*256 + k] = __float2half(src[k*256 + n]);
}

// ---------------- MSA LayerNorm -> fp16 ----------------
__global__ void ln_msa_kernel(const float* __restrict__ x,
                              const float* __restrict__ gamma,
                              const float* __restrict__ beta) {
    int row = blockIdx.x;
    int t = threadIdx.x;
    float v = x[(size_t)row*CM + t];
    float s1 = v, s2 = v*v;
    #pragma unroll
    for (int o = 16; o; o >>= 1) {
        s1 += __shfl_xor_sync(0xffffffffu, s1, o);
        s2 += __shfl_xor_sync(0xffffffffu, s2, o);
    }
    __shared__ float r1[8], r2[8];
    int w = t >> 5, lane = t & 31;
    if (lane == 0) { r1[w] = s1; r2[w] = s2; }
    __syncthreads();
    float ts1 = 0.f, ts2 = 0.f;
    #pragma unroll
    for (int i = 0; i < 8; ++i) { ts1 += r1[i]; ts2 += r2[i]; }
    float mu  = ts1 * (1.f/CM);
    float var = ts2 * (1.f/CM) - mu*mu;
    float rs  = rsqrtf(var + 1e-5f);
    g_mh[(size_t)row*CM + t] = __float2half((v - mu)*rs*gamma[t] + beta[t]);
}

// ---------------- pair LN + bias projection ----------------
__global__ void pair_bias_kernel(const float* __restrict__ z,
                                 const float* __restrict__ gamma,
                                 const float* __restrict__ beta,
                                 const float* __restrict__ wb,
                                 const float* __restrict__ bb) {
    int ij = blockIdx.x;
    int t  = threadIdx.x;             // 0..127
    float v = z[(size_t)ij*CZ + t];
    float s1 = v, s2 = v*v;
    #pragma unroll
    for (int o = 16; o; o >>= 1) {
        s1 += __shfl_xor_sync(0xffffffffu, s1, o);
        s2 += __shfl_xor_sync(0xffffffffu, s2, o);
    }
    __shared__ float r1[4], r2[4];
    int w = t >> 5, lane = t & 31;
    if (lane == 0) { r1[w] = s1; r2[w] = s2; }
    __syncthreads();
    float ts1 = r1[0]+r1[1]+r1[2]+r1[3];
    float ts2 = r2[0]+r2[1]+r2[2]+r2[3];
    float mu  = ts1 * (1.f/CZ);
    float var = ts2 * (1.f/CZ) - mu*mu;
    float rs  = rsqrtf(var + 1e-5f);
    float zn  = (v - mu)*rs*gamma[t] + beta[t];

    __shared__ float part[4][8];
    #pragma unroll
    for (int h = 0; h < H; ++h) {
        float p = zn * wb[t*H + h];
        #pragma unroll
        for (int o = 16; o; o >>= 1) p += __shfl_xor_sync(0xffffffffu, p, o);
        if (lane == 0) part[w][h] = p;
    }
    __syncthreads();
    if (t < H) {
        float sum = part[0][t] + part[1][t] + part[2][t] + part[3][t] + bb[t];
        g_bias[(size_t)t*(R*R) + ij] = sum;
    }
}

// =======================================================================
// fp16 GEMM with ldmatrix: C[M,N] = A[M,256] @ Bt[N,256]^T
// block 128x128, BK=32, 2-stage cp.async, 8 warps (4x2), warp 32x64
// EPI 0: fused QKVG epilogue (N=1024): q,k,v fp16; g = sigmoid(+bias) fp32
// EPI 1: +bias, fp32 store (N=256)
// =======================================================================
template<int EPI>
__global__ __launch_bounds__(256) void gemm_h(const __half* __restrict__ A,
                                              const __half* __restrict__ Bt,
                                              const float* __restrict__ bias,
                                              float* __restrict__ outF) {
    __shared__ __align__(16) __half As[2][128*40];
    __shared__ __align__(16) __half Bs[2][128*40];
    const int K = 256;
    int tid = threadIdx.x, lane = tid & 31, warp = tid >> 5;
    int g = lane >> 2, tg = lane & 3;
    int wm = warp >> 1, wn = warp & 1;
    int m0 = blockIdx.y * 128, n0 = blockIdx.x * 128;
    int aRow = lane & 15, aCol = (lane >> 4) * 8;
    int bRow = (lane & 7) + ((lane >> 4) << 3), bCol = ((lane >> 3) & 1) * 8;

    float acc[2][8][4];
    #pragma unroll
    for (int mt = 0; mt < 2; ++mt)
        #pragma unroll
        for (int nt = 0; nt < 8; ++nt)
            #pragma unroll
            for (int i = 0; i < 4; ++i) acc[mt][nt][i] = 0.f;

    #define GISSUE(kt, st) {                                                    \
        const __half* Ab = A  + (size_t)m0*K + (kt)*32;                         \
        const __half* Bb = Bt + (size_t)n0*K + (kt)*32;                         \
        _Pragma("unroll")                                                       \
        for (int l = 0; l < 2; ++l) {                                           \
            int idx = l*256 + tid; int row = idx >> 2, c8 = (idx & 3)*8;        \
            CP16(sptr(&As[st][row*40 + c8]), Ab + (size_t)row*K + c8);          \
            CP16(sptr(&Bs[st][row*40 + c8]), Bb + (size_t)row*K + c8);          \
        }                                                                       \
        CP_COMMIT();                                                            \
    }

    GISSUE(0, 0);
    for (int kt = 0; kt < 8; ++kt) {
        if (kt + 1 < 8) { GISSUE(kt+1, (kt+1)&1); CP_WAIT1(); }
        else CP_WAIT0();
        __syncthreads();
        int st = kt & 1;
        #pragma unroll
        for (int ks = 0; ks < 32; ks += 16) {
            unsigned a[2][4], b[4][4];
            #pragma unroll
            for (int mt = 0; mt < 2; ++mt)
                ldsm_x4(a[mt], sptr(&As[st][(wm*32 + mt*16 + aRow)*40 + ks + aCol]));
            #pragma unroll
            for (int nb = 0; nb < 4; ++nb)
                ldsm_x4(b[nb], sptr(&Bs[st][(wn*64 + nb*16 + bRow)*40 + ks + bCol]));
            #pragma unroll
            for (int mt = 0; mt < 2; ++mt)
                #pragma unroll
                for (int nb = 0; nb < 4; ++nb) {
                    mma16h(acc[mt][2*nb  ], a[mt], &b[nb][0]);
                    mma16h(acc[mt][2*nb+1], a[mt], &b[nb][2]);
                }
        }
        __syncthreads();
    }
    #undef GISSUE

    #pragma unroll
    for (int mt = 0; mt < 2; ++mt) {
        int row = m0 + wm*32 + mt*16 + g;
        #pragma unroll
        for (int nt = 0; nt < 8; ++nt) {
            int col = n0 + wn*64 + nt*8 + tg*2;
            float c0 = acc[mt][nt][0], c1 = acc[mt][nt][1];
            float c2 = acc[mt][nt][2], c3 = acc[mt][nt][3];
            if (EPI == 0) {
                int chunk = col >> 8, lc = col & 255;
                if (chunk == 3) {
                    float b0 = bias[lc], b1 = bias[lc+1];
                    float v0 = 1.f/(1.f + __expf(-(c0+b0)));
                    float v1 = 1.f/(1.f + __expf(-(c1+b1)));
                    float v2 = 1.f/(1.f + __expf(-(c2+b0)));
                    float v3 = 1.f/(1.f + __expf(-(c3+b1)));
                    *(float2*)(g_g + (size_t)row*256 + lc)     = make_float2(v0, v1);
                    *(float2*)(g_g + (size_t)(row+8)*256 + lc) = make_float2(v2, v3);
                } else {
                    __half* dst = (chunk == 0) ? g_qh : (chunk == 1) ? g_kh : g_vh;
                    *(unsigned*)(dst + (size_t)row*256 + lc)     = pk2(c0, c1);
                    *(unsigned*)(dst + (size_t)(row+8)*256 + lc) = pk2(c2, c3);
                }
            } else {
                float b0 = bias[col], b1 = bias[col+1];
                *(float2*)(outF + (size_t)row*256 + col)     = make_float2(c0+b0, c1+b1);
                *(float2*)(outF + (size_t)(row+8)*256 + col) = make_float2(c2+b0, c3+b1);
            }
        }
    }
}

// =======================================================================
// Fused flash attention: QK^T + bias -> softmax -> AV -> gate, per 64-q tile
// grid = S*H*4, 256 threads (8 warps: wm 0-3 x 16 rows, wn 0-1 x 128 cols)
// =======================================================================
__global__ __launch_bounds__(256) void attn_fused() {
    __shared__ __align__(16) __half Qs[64*40];
    __shared__ __align__(16) __half KVs[256*40];     // K, then V (reused)
    __shared__ float redm[64][2], reds[64][2];
    __shared__ float Ox[4*16*36];                    // wn=1 partial O
    int b = blockIdx.x;
    int sh = b >> 2, m0 = (b & 3)*64;
    int s = sh >> 3, h = sh & 7;
    int tid = threadIdx.x, lane = tid & 31, warp = tid >> 5;
    int g = lane >> 2, tg = lane & 3;
    int wm = warp >> 1, wn = warp & 1;
    int aRow = lane & 15, aCol = (lane >> 4) * 8;
    int bRow = (lane & 7) + ((lane >> 4) << 3), bCol = ((lane >> 3) & 1) * 8;
    int tRow = (lane & 7) + 8*((lane >> 3) & 1), tCol = 8*(lane >> 4);

    const __half* Qp = g_qh + (size_t)(s*R + m0)*256 + h*CH;
    const __half* Kp = g_kh + (size_t)(s*R)*256 + h*CH;
    const __half* Vp = g_vh + (size_t)(s*R)*256 + h*CH;

    // load Q (64x32) + K (256x32)
    {
        int row = tid >> 2, c8 = (tid & 3)*8;        // 256 chunks for Q
        CP16(sptr(&Qs[row*40 + c8]), Qp + (size_t)row*256 + c8);
    }
    #pragma unroll
    for (int l = 0; l < 4; ++l) {
        int idx = l*256 + tid; int row = idx >> 2, c8 = (idx & 3)*8;
        CP16(sptr(&KVs[row*40 + c8]), Kp + (size_t)row*256 + c8);
    }
    CP_COMMIT(); CP_WAIT0();
    __syncthreads();

    // QK^T
    float acc[16][4];
    #pragma unroll
    for (int nt = 0; nt < 16; ++nt)
        #pragma unroll
        for (int i = 0; i < 4; ++i) acc[nt][i] = 0.f;

    int rb = wm*16;
    #pragma unroll
    for (int ks = 0; ks < 32; ks += 16) {
        unsigned a[4];
        ldsm_x4(a, sptr(&Qs[(rb + aRow)*40 + ks + aCol]));
        #pragma unroll
        for (int nb = 0; nb < 8; ++nb) {
            unsigned bfr[4];
            ldsm_x4(bfr, sptr(&KVs[(wn*128 + nb*16 + bRow)*40 + ks + bCol]));
            mma16h(acc[2*nb  ], a, &bfr[0]);
            mma16h(acc[2*nb+1], a, &bfr[2]);
        }
    }
    __syncthreads();    // all K reads done -> reuse KVs for V

    // issue V load (overlaps softmax)
    #pragma unroll
    for (int l = 0; l < 4; ++l) {
        int idx = l*256 + tid; int row = idx >> 2, c8 = (idx & 3)*8;
        CP16(sptr(&KVs[row*40 + c8]), Vp + (size_t)row*256 + c8);
    }
    CP_COMMIT();

    // softmax over 256 cols (two wn halves reduced via smem)
    const float sc = 0.17677669529663687f;   // 1/sqrt(32)
    int rA = rb + g, rB = rb + g + 8;        // local rows
    const float* Bb = g_bias + (size_t)h*R*R + (size_t)m0*R;
    float mxA = -1e30f, mxB = -1e30f;
    #pragma unroll
    for (int nt = 0; nt < 16; ++nt) {
        int col = wn*128 + nt*8 + tg*2;
        float2 bA = *(const float2*)(Bb + (size_t)rA*R + col);
        float2 bB = *(const float2*)(Bb + (size_t)rB*R + col);
        acc[nt][0] = fmaf(acc[nt][0], sc, bA.x);
        acc[nt][1] = fmaf(acc[nt][1], sc, bA.y);
        acc[nt][2] = fmaf(acc[nt][2], sc, bB.x);
        acc[nt][3] = fmaf(acc[nt][3], sc, bB.y);
        mxA = fmaxf(mxA, fmaxf(acc[nt][0], acc[nt][1]));
        mxB = fmaxf(mxB, fmaxf(acc[nt][2], acc[nt][3]));
    }
    mxA = fmaxf(mxA, __shfl_xor_sync(0xffffffffu, mxA, 1));
    mxA = fmaxf(mxA, __shfl_xor_sync(0xffffffffu, mxA, 2));
    mxB = fmaxf(mxB, __shfl_xor_sync(0xffffffffu, mxB, 1));
    mxB = fmaxf(mxB, __shfl_xor_sync(0xffffffffu, mxB, 2));
    if (tg == 0) { redm[rA][wn] = mxA; redm[rB][wn] = mxB; }
    __syncthreads();
    float gA = fmaxf(redm[rA][0], redm[rA][1]);
    float gB = fmaxf(redm[rB][0], redm[rB][1]);

    float sA = 0.f, sB = 0.f;
    #pragma unroll
    for (int nt = 0; nt < 16; ++nt) {
        acc[nt][0] = __expf(acc[nt][0] - gA);
        acc[nt][1] = __expf(acc[nt][1] - gA);
        acc[nt][2] = __expf(acc[nt][2] - gB);
        acc[nt][3] = __expf(acc[nt][3] - gB);
        sA += acc[nt][0] + acc[nt][1];
        sB += acc[nt][2] + acc[nt][3];
    }
    sA += __shfl_xor_sync(0xffffffffu, sA, 1);
    sA += __shfl_xor_sync(0xffffffffu, sA, 2);
    sB += __shfl_xor_sync(0xffffffffu, sB, 1);
    sB += __shfl_xor_sync(0xffffffffu, sB, 2);
    if (tg == 0) { reds[rA][wn] = sA; reds[rB][wn] = sB; }
    __syncthreads();
    float iA = 1.f/(reds[rA][0] + reds[rA][1]);
    float iB = 1.f/(reds[rB][0] + reds[rB][1]);
    #pragma unroll
    for (int nt = 0; nt < 16; ++nt) {
        acc[nt][0] *= iA; acc[nt][1] *= iA;
        acc[nt][2] *= iB; acc[nt][3] *= iB;
    }

    CP_WAIT0();
    __syncthreads();    // V ready

    // AV: each warp contracts its 128-j half; W regs become A fragments
    float oacc[4][4];
    #pragma unroll
    for (int nt = 0; nt < 4; ++nt)
        #pragma unroll
        for (int i = 0; i < 4; ++i) oacc[nt][i] = 0.f;

    #pragma unroll
    for (int t = 0; t < 8; ++t) {        // k16 tiles over this warp's j range
        unsigned af[4];
        af[0] = pk2(acc[2*t  ][0], acc[2*t  ][1]);
        af[1] = pk2(acc[2*t  ][2], acc[2*t  ][3]);
        af[2] = pk2(acc[2*t+1][0], acc[2*t+1][1]);
        af[3] = pk2(acc[2*t+1][2], acc[2*t+1][3]);
        int j0 = wn*128 + t*16;
        #pragma unroll
        for (int nb = 0; nb < 2; ++nb) {
            unsigned bfr[4];
            ldsm_x4t(bfr, sptr(&KVs[(j0 + tRow)*40 + nb*16 + tCol]));
            mma16h(oacc[2*nb  ], af, &bfr[0]);
            mma16h(oacc[2*nb+1], af, &bfr[2]);
        }
    }

    // combine wn halves, gate, store
    if (wn == 1) {
        #pragma unroll
        for (int nt = 0; nt < 4; ++nt) {
            int col = nt*8 + tg*2;
            Ox[(wm*16 + g    )*36 + col    ] = oacc[nt][0];
            Ox[(wm*16 + g    )*36 + col + 1] = oacc[nt][1];
            Ox[(wm*16 + g + 8)*36 + col    ] = oacc[nt][2];
            Ox[(wm*16 + g + 8)*36 + col + 1] = oacc[nt][3];
        }
    }
    __syncthreads();
    if (wn == 0) {
        const float* Gp = g_g  + (size_t)(s*R + m0)*256 + h*CH;
        __half*      Op = g_oh + (size_t)(s*R + m0)*256 + h*CH;
        #pragma unroll
        for (int nt = 0; nt < 4; ++nt) {
            int col = nt*8 + tg*2;
            int r0 = wm*16 + g, r1 = r0 + 8;
            float v0 = oacc[nt][0] + Ox[r0*36 + col];
            float v1 = oacc[nt][1] + Ox[r0*36 + col + 1];
            float v2 = oacc[nt][2] + Ox[r1*36 + col];
            float v3 = oacc[nt][3] + Ox[r1*36 + col + 1];
            float2 g0 = *(const float2*)(Gp + (size_t)r0*256 + col);
            float2 g1 = *(const float2*)(Gp + (size_t)r1*256 + col);
            *(unsigned*)(Op + (size_t)r0*256 + col) = pk2(v0*g0.x, v1*g0.y);
            *(unsigned*)(Op + (size_t)r1*256 + col) = pk2(v2*g1.x, v3*g1.y);
        }
    }
}

// ---------------------------------------------------------------------------
extern "C" void kernel_launch(void* const* d_in, const int* in_sizes, int n_in,
                              void* d_out, int out_size) {
    const float* msa      = (const float*)d_in[0];
    const float* pair     = (const float*)d_in[1];
    const float* ln_msa_g = (const float*)d_in[2];
    const float* ln_msa_b = (const float*)d_in[3];
    const float* ln_pr_g  = (const float*)d_in[4];
    const float* ln_pr_b  = (const float*)d_in[5];
    const float* w_q      = (const float*)d_in[6];
    const float* w_k      = (const float*)d_in[7];
    const float* w_v      = (const float*)d_in[8];
    const float* w_g      = (const float*)d_in[9];
    const float* b_g      = (const float*)d_in[10];
    const float* w_b      = (const float*)d_in[11];
    const float* b_b      = (const float*)d_in[12];
    const float* w_o      = (const float*)d_in[13];
    const float* b_o      = (const float*)d_in[14];

    __half *pm, *po, *pw;
    cudaGetSymbolAddress((void**)&pm, g_mh);
    cudaGetSymbolAddress((void**)&po, g_oh);
    cudaGetSymbolAddress((void**)&pw, g_wt);

    // 1. prep: weights fp16+transpose, LN, pair bias
    pack_w<<<1280, 256>>>(w_q, w_k, w_v, w_g, w_o);
    ln_msa_kernel<<<MROWS, 256>>>(msa, ln_msa_g, ln_msa_b);
    pair_bias_kernel<<<R*R, 128>>>(pair, ln_pr_g, ln_pr_b, w_b, b_b);

    // 2. fused Q/K/V/G projection: [32768,256] x [256,1024]
    gemm_h<0><<<dim3(8, 256), 256>>>(pm, pw, b_g, nullptr);

    // 3. fused attention
    attn_fused<<<S*H*4, 256>>>();

    // 4. output projection + bias
    gemm_h<1><<<dim3(2, 256), 256>>>(po, pw + 4*65536, b_o, (float*)d_out);
}